// round 3
// baseline (speedup 1.0000x reference)
#include <cuda_runtime.h>
#include <cuda_bf16.h>

// Problem constants
#define B_DIM 128
#define L_DIM 1024
#define D_DIM 128
#define DVF   32          // D/4 float4 groups (full row)
#define DT    8           // float4 groups per D-tile (D split 4 ways)
#define NDT   4
#define TSTART 256        // output start positions per L tile
#define NPOS  287         // TSTART + 31 halo positions (mask)
#define NS4   284         // TSTART + 28 sliding-4-sum positions
#define NTHREADS 512

// Output row offsets for window sizes 4, 8, 16, 32
#define OFF4  0
#define OFF8  1021
#define OFF16 2038
#define OFF32 3047
#define ROWS  4040

// Shared memory (floats):
//   s4  : NS4 * DT * 4   sliding 4-sums
//   inv : 4 * TSTART
//   msk : NPOS ints (padded to 288)
#define SMEM_FLOATS (NS4 * DT * 4 + 4 * TSTART + 288)
#define SMEM_BYTES  (SMEM_FLOATS * 4)

__device__ __forceinline__ float4 add4(float4 a, float4 b) {
    return make_float4(a.x + b.x, a.y + b.y, a.z + b.z, a.w + b.w);
}
__device__ __forceinline__ float4 scl4(float4 a, float s) {
    return make_float4(a.x * s, a.y * s, a.z * s, a.w * s);
}

extern __shared__ float smem_raw[];

__global__ __launch_bounds__(NTHREADS, 3)
void msse_kernel(const float* __restrict__ x,
                 const int* __restrict__ mask,
                 float* __restrict__ out)
{
    const int s0    = blockIdx.x * TSTART;    // global start of this L tile
    const int dbase = blockIdx.y * DT;        // float4-group base of D tile
    const int b     = blockIdx.z;
    const int tid   = threadIdx.x;

    float4* s4  = reinterpret_cast<float4*>(smem_raw);           // NS4*DT f4
    float*  inv = reinterpret_cast<float*>(s4 + NS4 * DT);       // 4*TSTART
    int*    msk = reinterpret_cast<int*>(inv + 4 * TSTART);      // NPOS

    // ---- phase 1: load mask tile (with halo), zero-pad past L ----
    const int* mrow = mask + (size_t)b * L_DIM;
    for (int p = tid; p < NPOS; p += NTHREADS) {
        int g = s0 + p;
        msk[p] = (g < L_DIM) ? mrow[g] : 0;
    }
    __syncthreads();

    const float4* xrow = reinterpret_cast<const float4*>(x + (size_t)b * L_DIM * D_DIM);
    const float4 fz = make_float4(0.f, 0.f, 0.f, 0.f);

    // ---- phase 2a: build s4 directly from global (rolling window, P=5 run) ----
    if (tid < 57 * 8) {
        const int q  = tid & 7;
        const int r  = tid >> 3;        // 0..56
        const int p0 = r * 5;

        #define MLOAD(p) (msk[(p)] ? xrow[(size_t)(s0 + (p)) * DVF + dbase + q] : fz)
        float4 w0 = MLOAD(p0);
        float4 w1 = MLOAD(p0 + 1);
        float4 w2 = MLOAD(p0 + 2);
        #pragma unroll
        for (int i = 0; i < 5; i++) {
            int p = p0 + i;
            if (p < NS4) {
                float4 w3 = MLOAD(p + 3);
                s4[p * DT + q] = add4(add4(w0, w1), add4(w2, w3));
                w0 = w1; w1 = w2; w2 = w3;
            }
        }
        #undef MLOAD
    }

    // ---- phase 2b: per-start window-length reciprocals ----
    if (tid < TSTART) {
        int j = tid;
        int c = 0;
        #pragma unroll
        for (int k = 0; k < 4; k++)  c += msk[j + k];
        int c4 = c;
        #pragma unroll
        for (int k = 4; k < 8; k++)  c += msk[j + k];
        int c8 = c;
        #pragma unroll
        for (int k = 8; k < 16; k++) c += msk[j + k];
        int c16 = c;
        #pragma unroll
        for (int k = 16; k < 32; k++) c += msk[j + k];
        int c32 = c;
        inv[0 * TSTART + j] = 1.0f / (float)(c4  > 1 ? c4  : 1);
        inv[1 * TSTART + j] = 1.0f / (float)(c8  > 1 ? c8  : 1);
        inv[2 * TSTART + j] = 1.0f / (float)(c16 > 1 ? c16 : 1);
        inv[3 * TSTART + j] = 1.0f / (float)(c32 > 1 ? c32 : 1);
    }
    __syncthreads();

    // ---- phase 3: outputs. Each thread: fixed (q, jm), R=4 starts strided by 4,
    //      register ring of 8 s4 values -> 11 LDS per 4 starts (2.75/start) ----
    {
        const int q  = tid & 7;
        const int jm = (tid >> 3) & 3;
        const int c  = tid >> 5;        // 0..15
        const int t0 = c * 4;           // t index base; starts j = jm + 4*t
        const int oq = dbase + q;

        float4* outb = reinterpret_cast<float4*>(out + (size_t)b * ROWS * D_DIM);

        float4 r[8];
        #pragma unroll
        for (int k = 0; k < 8; k++)
            r[k] = s4[(jm + 4 * (t0 + k)) * DT + q];

        #pragma unroll
        for (int m = 0; m < 4; m++) {
            const int j  = jm + 4 * (t0 + m);   // local start
            const int gi = s0 + j;              // global start

            const float i4  = inv[0 * TSTART + j];
            const float i8  = inv[1 * TSTART + j];
            const float i16 = inv[2 * TSTART + j];
            const float i32 = inv[3 * TSTART + j];

            float4 acc = r[0];
            if (gi <= L_DIM - 4)
                outb[(OFF4  + gi) * DVF + oq] = scl4(acc, i4);
            acc = add4(acc, r[1]);
            if (gi <= L_DIM - 8)
                outb[(OFF8  + gi) * DVF + oq] = scl4(acc, i8);
            acc = add4(acc, add4(r[2], r[3]));
            if (gi <= L_DIM - 16)
                outb[(OFF16 + gi) * DVF + oq] = scl4(acc, i16);
            acc = add4(acc, add4(add4(r[4], r[5]), add4(r[6], r[7])));
            if (gi <= L_DIM - 32)
                outb[(OFF32 + gi) * DVF + oq] = scl4(acc, i32);

            // shift ring, load next s4
            #pragma unroll
            for (int k = 0; k < 7; k++) r[k] = r[k + 1];
            if (m < 3)
                r[7] = s4[(jm + 4 * (t0 + m + 8)) * DT + q];
        }
    }
}

extern "C" void kernel_launch(void* const* d_in, const int* in_sizes, int n_in,
                              void* d_out, int out_size)
{
    const float* x    = (const float*)d_in[0];
    const int*   mask = (const int*)d_in[1];
    float*       out  = (float*)d_out;

    cudaFuncSetAttribute(msse_kernel,
                         cudaFuncAttributeMaxDynamicSharedMemorySize, SMEM_BYTES);

    dim3 grid(L_DIM / TSTART, NDT, B_DIM);   // 4 x 4 x 128 = 2048 CTAs
    msse_kernel<<<grid, NTHREADS, SMEM_BYTES>>>(x, mask, out);
}

// round 4
// speedup vs baseline: 1.2306x; 1.2306x over previous
#include <cuda_runtime.h>
#include <cuda_bf16.h>

// Problem constants
#define B_DIM 128
#define L_DIM 1024
#define D_DIM 128
#define DVF   32          // D/4 float4 groups (full row)
#define DT    8           // float4 groups per D-tile (D split 4 ways)
#define NDT   4
#define TSTART 128        // output start positions per L tile
#define NPOS  159         // TSTART + 31 halo positions (mask)
#define NS4   156         // TSTART + 28 sliding-4-sum positions
#define NTHREADS 512

// Output row offsets for window sizes 4, 8, 16, 32
#define OFF4  0
#define OFF8  1021
#define OFF16 2038
#define OFF32 3047
#define ROWS  4040

// Shared memory (floats):
//   s4  : NS4 * DT * 4   sliding 4-sums
//   inv : 4 * TSTART
//   msk : NPOS ints (padded to 160)
#define SMEM_FLOATS (NS4 * DT * 4 + 4 * TSTART + 160)
#define SMEM_BYTES  (SMEM_FLOATS * 4)

__device__ __forceinline__ float4 add4(float4 a, float4 b) {
    return make_float4(a.x + b.x, a.y + b.y, a.z + b.z, a.w + b.w);
}
__device__ __forceinline__ float4 scl4(float4 a, float s) {
    return make_float4(a.x * s, a.y * s, a.z * s, a.w * s);
}

extern __shared__ float smem_raw[];

__global__ __launch_bounds__(NTHREADS, 4)
void msse_kernel(const float* __restrict__ x,
                 const int* __restrict__ mask,
                 float* __restrict__ out)
{
    const int s0    = blockIdx.x * TSTART;    // global start of this L tile
    const int dbase = blockIdx.y * DT;        // float4-group base of D tile
    const int b     = blockIdx.z;
    const int tid   = threadIdx.x;

    float4* s4  = reinterpret_cast<float4*>(smem_raw);           // NS4*DT f4
    float*  inv = reinterpret_cast<float*>(s4 + NS4 * DT);       // 4*TSTART
    int*    msk = reinterpret_cast<int*>(inv + 4 * TSTART);      // NPOS

    // ---- phase 1: load mask tile (with halo), zero-pad past L ----
    const int* mrow = mask + (size_t)b * L_DIM;
    for (int p = tid; p < NPOS; p += NTHREADS) {
        int g = s0 + p;
        msk[p] = (g < L_DIM) ? mrow[g] : 0;
    }
    __syncthreads();

    const float4* xrow = reinterpret_cast<const float4*>(x + (size_t)b * L_DIM * D_DIM);
    const float4 fz = make_float4(0.f, 0.f, 0.f, 0.f);

    // ---- phase 2a: build s4 directly from global (4 masked loads each).
    //      msk is zero past L, so no OOB loads. Warp = 4 rows x 8 q -> each
    //      load step touches 4 coalesced 128B lines. L2 absorbs the 4x reuse. ----
    for (int i = tid; i < NS4 * DT; i += NTHREADS) {
        int p = i >> 3;
        int q = i & 7;
        const float4* base = xrow + (size_t)(s0 + p) * DVF + dbase + q;
        float4 acc = fz;
        #pragma unroll
        for (int k = 0; k < 4; k++) {
            if (msk[p + k]) acc = add4(acc, base[k * DVF]);
        }
        s4[i] = acc;
    }

    // ---- phase 2b: per-start window-length reciprocals ----
    if (tid < TSTART) {
        int j = tid;
        int c = 0;
        #pragma unroll
        for (int k = 0; k < 4; k++)  c += msk[j + k];
        int c4 = c;
        #pragma unroll
        for (int k = 4; k < 8; k++)  c += msk[j + k];
        int c8 = c;
        #pragma unroll
        for (int k = 8; k < 16; k++) c += msk[j + k];
        int c16 = c;
        #pragma unroll
        for (int k = 16; k < 32; k++) c += msk[j + k];
        int c32 = c;
        inv[0 * TSTART + j] = 1.0f / (float)(c4  > 1 ? c4  : 1);
        inv[1 * TSTART + j] = 1.0f / (float)(c8  > 1 ? c8  : 1);
        inv[2 * TSTART + j] = 1.0f / (float)(c16 > 1 ? c16 : 1);
        inv[3 * TSTART + j] = 1.0f / (float)(c32 > 1 ? c32 : 1);
    }
    __syncthreads();

    // ---- phase 3: all 4 window outputs per (start j, d-group q).
    //      Sequential consumption keeps register count low. ----
    float4* outb = reinterpret_cast<float4*>(out + (size_t)b * ROWS * D_DIM);
    for (int it = tid; it < TSTART * DT; it += NTHREADS) {
        int j = it >> 3;          // local start; warp covers 4 j rows -> coalesced
        int q = it & 7;
        int gi = s0 + j;          // global start index
        int oq = dbase + q;       // output float4 column

        const float i4  = inv[0 * TSTART + j];
        const float i8  = inv[1 * TSTART + j];
        const float i16 = inv[2 * TSTART + j];
        const float i32 = inv[3 * TSTART + j];

        float4 acc = s4[(j     ) * DT + q];
        if (gi <= L_DIM - 4)
            outb[(OFF4  + gi) * DVF + oq] = scl4(acc, i4);

        acc = add4(acc, s4[(j + 4) * DT + q]);
        if (gi <= L_DIM - 8)
            outb[(OFF8  + gi) * DVF + oq] = scl4(acc, i8);

        acc = add4(acc, add4(s4[(j + 8) * DT + q], s4[(j + 12) * DT + q]));
        if (gi <= L_DIM - 16)
            outb[(OFF16 + gi) * DVF + oq] = scl4(acc, i16);

        acc = add4(acc, add4(add4(s4[(j + 16) * DT + q], s4[(j + 20) * DT + q]),
                             add4(s4[(j + 24) * DT + q], s4[(j + 28) * DT + q])));
        if (gi <= L_DIM - 32)
            outb[(OFF32 + gi) * DVF + oq] = scl4(acc, i32);
    }
}

extern "C" void kernel_launch(void* const* d_in, const int* in_sizes, int n_in,
                              void* d_out, int out_size)
{
    const float* x    = (const float*)d_in[0];
    const int*   mask = (const int*)d_in[1];
    float*       out  = (float*)d_out;

    cudaFuncSetAttribute(msse_kernel,
                         cudaFuncAttributeMaxDynamicSharedMemorySize, SMEM_BYTES);

    dim3 grid(L_DIM / TSTART, NDT, B_DIM);   // 8 x 4 x 128 = 4096 CTAs
    msse_kernel<<<grid, NTHREADS, SMEM_BYTES>>>(x, mask, out);
}

// round 5
// speedup vs baseline: 1.2320x; 1.0011x over previous
#include <cuda_runtime.h>
#include <cuda_bf16.h>

// Problem constants
#define B_DIM 128
#define L_DIM 1024
#define D_DIM 128
#define DVF   32          // D/4 float4 groups (full row)
#define DT    8           // float4 groups per D-tile (D split 4 ways)
#define NDT   4
#define TSTART 128        // output start positions per L tile
#define NPOS  159         // TSTART + 31 halo positions (mask)
#define NS4   160         // TSTART + 28 sliding-4-sum positions (pad to 160; j+36 max read = 159)
#define NTHREADS 512

// Output row offsets for window sizes 4, 8, 16, 32
#define OFF4  0
#define OFF8  1021
#define OFF16 2038
#define OFF32 3047
#define ROWS  4040

// Shared memory (floats):
//   s4  : NS4 * DT * 4   sliding 4-sums
//   inv : 4 * TSTART
//   msk : NPOS ints (padded to 160)
#define SMEM_FLOATS (NS4 * DT * 4 + 4 * TSTART + 160)
#define SMEM_BYTES  (SMEM_FLOATS * 4)

__device__ __forceinline__ float4 add4(float4 a, float4 b) {
    return make_float4(a.x + b.x, a.y + b.y, a.z + b.z, a.w + b.w);
}
__device__ __forceinline__ float4 scl4(float4 a, float s) {
    return make_float4(a.x * s, a.y * s, a.z * s, a.w * s);
}

extern __shared__ float smem_raw[];

__global__ __launch_bounds__(NTHREADS, 4)
void msse_kernel(const float* __restrict__ x,
                 const int* __restrict__ mask,
                 float* __restrict__ out)
{
    const int s0    = blockIdx.x * TSTART;    // global start of this L tile
    const int dbase = blockIdx.y * DT;        // float4-group base of D tile
    const int b     = blockIdx.z;
    const int tid   = threadIdx.x;

    float4* s4  = reinterpret_cast<float4*>(smem_raw);           // NS4*DT f4
    float*  inv = reinterpret_cast<float*>(s4 + NS4 * DT);       // 4*TSTART
    int*    msk = reinterpret_cast<int*>(inv + 4 * TSTART);      // NPOS

    // ---- phase 1: load mask tile (with halo), zero-pad past L ----
    const int* mrow = mask + (size_t)b * L_DIM;
    for (int p = tid; p < NPOS; p += NTHREADS) {
        int g = s0 + p;
        msk[p] = (g < L_DIM) ? mrow[g] : 0;
    }
    __syncthreads();

    const float4* xrow = reinterpret_cast<const float4*>(x + (size_t)b * L_DIM * D_DIM);
    const float4 fz = make_float4(0.f, 0.f, 0.f, 0.f);

    // ---- phase 2a: build s4 directly from global (4 masked loads each).
    //      msk is zero past L (and entries >= NPOS map to padded zeros below),
    //      so no OOB loads. L2 absorbs the 4x row reuse. ----
    for (int i = tid; i < NS4 * DT; i += NTHREADS) {
        int p = i >> 3;
        int q = i & 7;
        float4 acc = fz;
        if (p < NS4 - 4 + 1 && p <= NPOS - 1) { /* always true for p < 156 */ }
        if (p < 156) {
            const float4* base = xrow + (size_t)(s0 + p) * DVF + dbase + q;
            #pragma unroll
            for (int k = 0; k < 4; k++) {
                if (msk[p + k]) acc = add4(acc, base[k * DVF]);
            }
        }
        s4[i] = acc;   // entries 156..159 are zero padding (reads at j+32..j+36 never used beyond 155, safe)
    }

    // ---- phase 2b: per-start window-length reciprocals ----
    if (tid < TSTART) {
        int j = tid;
        int c = 0;
        #pragma unroll
        for (int k = 0; k < 4; k++)  c += msk[j + k];
        int c4 = c;
        #pragma unroll
        for (int k = 4; k < 8; k++)  c += msk[j + k];
        int c8 = c;
        #pragma unroll
        for (int k = 8; k < 16; k++) c += msk[j + k];
        int c16 = c;
        #pragma unroll
        for (int k = 16; k < 32; k++) c += msk[j + k];
        int c32 = c;
        inv[0 * TSTART + j] = 1.0f / (float)(c4  > 1 ? c4  : 1);
        inv[1 * TSTART + j] = 1.0f / (float)(c8  > 1 ? c8  : 1);
        inv[2 * TSTART + j] = 1.0f / (float)(c16 > 1 ? c16 : 1);
        inv[3 * TSTART + j] = 1.0f / (float)(c32 > 1 ? c32 : 1);
    }
    __syncthreads();

    // ---- phase 3: pair-start sweep. Each thread produces ALL windows for
    //      starts j0 and j1=j0+4 from one pass over a0..a8 (9 LDS / 2 starts).
    //      Warp = 4 consecutive j rows x 8 q -> conflict-free 512B LDS rows. ----
    {
        const int q   = tid & 7;
        const int idx = tid >> 3;        // 0..63
        const int jm  = idx & 3;
        const int k   = idx >> 2;        // 0..15
        const int j0  = jm + 8 * k;      // first start of pair
        const int j1  = j0 + 4;
        const int gi0 = s0 + j0;
        const int gi1 = s0 + j1;
        const int oq  = dbase + q;

        float4* outb = reinterpret_cast<float4*>(out + (size_t)b * ROWS * D_DIM);
        const float4* sp = s4 + j0 * DT + q;   // a_k = sp[k*4*DT]

        // a0
        float4 a    = sp[0];
        float4 accA = a;                                   // j0 running sum
        if (gi0 <= L_DIM - 4)
            outb[(OFF4 + gi0) * DVF + oq] = scl4(a, inv[0 * TSTART + j0]);
        // a1
        a = sp[4 * DT];
        float4 accB = a;                                   // j1 running sum
        if (gi1 <= L_DIM - 4)
            outb[(OFF4 + gi1) * DVF + oq] = scl4(a, inv[0 * TSTART + j1]);
        accA = add4(accA, a);
        if (gi0 <= L_DIM - 8)
            outb[(OFF8 + gi0) * DVF + oq] = scl4(accA, inv[1 * TSTART + j0]);
        // a2
        a = sp[8 * DT];
        accB = add4(accB, a);
        if (gi1 <= L_DIM - 8)
            outb[(OFF8 + gi1) * DVF + oq] = scl4(accB, inv[1 * TSTART + j1]);
        accA = add4(accA, a);
        // a3
        a = sp[12 * DT];
        accA = add4(accA, a);
        if (gi0 <= L_DIM - 16)
            outb[(OFF16 + gi0) * DVF + oq] = scl4(accA, inv[2 * TSTART + j0]);
        accB = add4(accB, a);
        // a4
        a = sp[16 * DT];
        accB = add4(accB, a);
        if (gi1 <= L_DIM - 16)
            outb[(OFF16 + gi1) * DVF + oq] = scl4(accB, inv[2 * TSTART + j1]);
        accA = add4(accA, a);
        // a5
        a = sp[20 * DT];
        accA = add4(accA, a);
        accB = add4(accB, a);
        // a6
        a = sp[24 * DT];
        accA = add4(accA, a);
        accB = add4(accB, a);
        // a7
        a = sp[28 * DT];
        accA = add4(accA, a);
        if (gi0 <= L_DIM - 32)
            outb[(OFF32 + gi0) * DVF + oq] = scl4(accA, inv[3 * TSTART + j0]);
        accB = add4(accB, a);
        // a8
        a = sp[32 * DT];
        accB = add4(accB, a);
        if (gi1 <= L_DIM - 32)
            outb[(OFF32 + gi1) * DVF + oq] = scl4(accB, inv[3 * TSTART + j1]);
    }
}

extern "C" void kernel_launch(void* const* d_in, const int* in_sizes, int n_in,
                              void* d_out, int out_size)
{
    const float* x    = (const float*)d_in[0];
    const int*   mask = (const int*)d_in[1];
    float*       out  = (float*)d_out;

    cudaFuncSetAttribute(msse_kernel,
                         cudaFuncAttributeMaxDynamicSharedMemorySize, SMEM_BYTES);

    dim3 grid(L_DIM / TSTART, NDT, B_DIM);   // 8 x 4 x 128 = 4096 CTAs
    msse_kernel<<<grid, NTHREADS, SMEM_BYTES>>>(x, mask, out);
}